// round 2
// baseline (speedup 1.0000x reference)
#include <cuda_runtime.h>
#include <math.h>

#define THREADS 256
#define TB 64            // rows per block
#define KC 32            // K chunk for w1 staging
#define XSTRIDE 772      // D=771 padded to 772 (row stride in smem, conflict-free)
#define DDIM 771
#define HDIM 96

// packed fp32x2 FMA (Blackwell FFMA2): 2 MACs per lane per instr
__device__ __forceinline__ unsigned long long ffma2(unsigned long long a,
                                                    unsigned long long b,
                                                    unsigned long long c) {
    unsigned long long d;
    asm("fma.rn.f32x2 %0, %1, %2, %3;" : "=l"(d) : "l"(a), "l"(b), "l"(c));
    return d;
}

__device__ __forceinline__ unsigned long long bcast2(float x) {
    unsigned long long r;
    asm("mov.b64 %0, {%1, %1};" : "=l"(r) : "f"(x));
    return r;
}

__device__ __forceinline__ float gelu_exact(float v) {
    return 0.5f * v * (1.0f + erff(v * 0.70710678118654752440f));
}

extern __shared__ float smem[];

__global__ __launch_bounds__(THREADS, 1)
void fusion_head_kernel(const float* __restrict__ emb,
                        const float* __restrict__ tree,
                        const float* __restrict__ gamma,
                        const float* __restrict__ beta,
                        const float* __restrict__ w1,
                        const float* __restrict__ b1,
                        const float* __restrict__ w2,
                        const float* __restrict__ b2,
                        float* __restrict__ out)
{
    float* sx = smem;                       // [64][772] normalized x
    float* sw = smem + TB * XSTRIDE;        // double buffer: 2 x [32][96]

    const int tid  = threadIdx.x;
    const int lane = tid & 31;
    const int warp = tid >> 5;
    const long long rowbase = (long long)blockIdx.x * TB;

    // ---- prefetch w1 chunk 0 into registers (overlaps with LayerNorm) ----
    float4 wpre[3];
    {
        const float4* src = (const float4*)w1;   // chunk0: 32*96 floats = 768 float4, fully valid
        #pragma unroll
        for (int k = 0; k < 3; ++k)
            wpre[k] = src[tid + THREADS * k];
    }

    // ---- Phase 1: concat + LayerNorm -> sx (one warp handles 8 rows) ----
    #pragma unroll
    for (int i = 0; i < 8; ++i) {
        const int rt = warp * 8 + i;
        const float4* e4 = (const float4*)(emb + (rowbase + rt) * 768);
        float4 v[6];
        float s = 0.f, ss = 0.f;
        #pragma unroll
        for (int k = 0; k < 6; ++k) {
            v[k] = e4[lane + 32 * k];
            s  += v[k].x + v[k].y + v[k].z + v[k].w;
            ss += v[k].x * v[k].x + v[k].y * v[k].y + v[k].z * v[k].z + v[k].w * v[k].w;
        }
        float tv = 0.f;
        if (lane < 3) tv = tree[(rowbase + rt) * 3 + lane];
        s += tv; ss += tv * tv;
        #pragma unroll
        for (int m = 16; m > 0; m >>= 1) {
            s  += __shfl_xor_sync(0xffffffffu, s, m);
            ss += __shfl_xor_sync(0xffffffffu, ss, m);
        }
        const float mu   = s * (1.0f / 771.0f);
        const float rstd = rsqrtf(ss * (1.0f / 771.0f) - mu * mu + 1e-5f);
        float* xr = sx + rt * XSTRIDE;
        #pragma unroll
        for (int k = 0; k < 6; ++k) {
            const int d4 = lane + 32 * k;
            float4 g  = ((const float4*)gamma)[d4];
            float4 bb = ((const float4*)beta)[d4];
            float4 o;
            o.x = (v[k].x - mu) * rstd * g.x + bb.x;
            o.y = (v[k].y - mu) * rstd * g.y + bb.y;
            o.z = (v[k].z - mu) * rstd * g.z + bb.z;
            o.w = (v[k].w - mu) * rstd * g.w + bb.w;
            ((float4*)xr)[d4] = o;
        }
        if (lane < 3) {
            const int d = 768 + lane;
            xr[d] = (tv - mu) * rstd * gamma[d] + beta[d];
        }
    }

    // commit w chunk 0 to smem buffer 0
    {
        float4* dst = (float4*)sw;
        #pragma unroll
        for (int k = 0; k < 3; ++k)
            dst[tid + THREADS * k] = wpre[k];
    }
    __syncthreads();

    // ---- Phase 2: GEMM1 (x[64,771] @ w1[771,96]), f32x2 packed accumulators ----
    const int cg = tid & 15;   // column group: cols 6*cg .. 6*cg+5  (3 f32x2 pairs)
    const int rg = tid >> 4;   // row group:    rows 4*rg .. 4*rg+3

    const float* xr0 = sx + (4 * rg + 0) * XSTRIDE;
    const float* xr1 = sx + (4 * rg + 1) * XSTRIDE;
    const float* xr2 = sx + (4 * rg + 2) * XSTRIDE;
    const float* xr3 = sx + (4 * rg + 3) * XSTRIDE;

    unsigned long long acc[4][3];
    #pragma unroll
    for (int i = 0; i < 4; ++i)
        #pragma unroll
        for (int j = 0; j < 3; ++j)
            acc[i][j] = 0ull;

    const int NCH = (DDIM + KC - 1) / KC;   // 25 chunks (24 full + tail of 3)

    for (int ch = 0; ch < NCH; ++ch) {
        const int d0   = ch * KC;
        const int kcur = (DDIM - d0 < KC) ? (DDIM - d0) : KC;
        const bool hasnext = (ch + 1 < NCH);

        // issue prefetch of next chunk (latency hidden by compute below)
        if (hasnext) {
            const int nd0 = d0 + KC;
            const int nk  = (DDIM - nd0 < KC) ? (DDIM - nd0) : KC;
            const float4* src = (const float4*)(w1 + (size_t)nd0 * HDIM);
            #pragma unroll
            for (int k = 0; k < 3; ++k) {
                const int f4 = tid + THREADS * k;
                if (f4 < nk * (HDIM / 4)) wpre[k] = src[f4];
            }
        }

        const float* wb = sw + (ch & 1) * (KC * HDIM);

        if (kcur == KC) {
            #pragma unroll 8
            for (int dd = 0; dd < KC; ++dd) {
                const float* wrow = wb + dd * HDIM + 6 * cg;
                const unsigned long long w0 = *(const unsigned long long*)(wrow);
                const unsigned long long w1v = *(const unsigned long long*)(wrow + 2);
                const unsigned long long w2v = *(const unsigned long long*)(wrow + 4);
                const int d = d0 + dd;
                unsigned long long x0 = bcast2(xr0[d]);
                unsigned long long x1 = bcast2(xr1[d]);
                unsigned long long x2 = bcast2(xr2[d]);
                unsigned long long x3 = bcast2(xr3[d]);
                acc[0][0] = ffma2(x0, w0, acc[0][0]);
                acc[0][1] = ffma2(x0, w1v, acc[0][1]);
                acc[0][2] = ffma2(x0, w2v, acc[0][2]);
                acc[1][0] = ffma2(x1, w0, acc[1][0]);
                acc[1][1] = ffma2(x1, w1v, acc[1][1]);
                acc[1][2] = ffma2(x1, w2v, acc[1][2]);
                acc[2][0] = ffma2(x2, w0, acc[2][0]);
                acc[2][1] = ffma2(x2, w1v, acc[2][1]);
                acc[2][2] = ffma2(x2, w2v, acc[2][2]);
                acc[3][0] = ffma2(x3, w0, acc[3][0]);
                acc[3][1] = ffma2(x3, w1v, acc[3][1]);
                acc[3][2] = ffma2(x3, w2v, acc[3][2]);
            }
        } else {
            for (int dd = 0; dd < kcur; ++dd) {
                const float* wrow = wb + dd * HDIM + 6 * cg;
                const unsigned long long w0 = *(const unsigned long long*)(wrow);
                const unsigned long long w1v = *(const unsigned long long*)(wrow + 2);
                const unsigned long long w2v = *(const unsigned long long*)(wrow + 4);
                const int d = d0 + dd;
                unsigned long long x0 = bcast2(xr0[d]);
                unsigned long long x1 = bcast2(xr1[d]);
                unsigned long long x2 = bcast2(xr2[d]);
                unsigned long long x3 = bcast2(xr3[d]);
                acc[0][0] = ffma2(x0, w0, acc[0][0]);
                acc[0][1] = ffma2(x0, w1v, acc[0][1]);
                acc[0][2] = ffma2(x0, w2v, acc[0][2]);
                acc[1][0] = ffma2(x1, w0, acc[1][0]);
                acc[1][1] = ffma2(x1, w1v, acc[1][1]);
                acc[1][2] = ffma2(x1, w2v, acc[1][2]);
                acc[2][0] = ffma2(x2, w0, acc[2][0]);
                acc[2][1] = ffma2(x2, w1v, acc[2][1]);
                acc[2][2] = ffma2(x2, w2v, acc[2][2]);
                acc[3][0] = ffma2(x3, w0, acc[3][0]);
                acc[3][1] = ffma2(x3, w1v, acc[3][1]);
                acc[3][2] = ffma2(x3, w2v, acc[3][2]);
            }
        }

        // commit prefetched chunk to the other buffer (its prior readers
        // finished at the sync that ended iteration ch-1)
        if (hasnext) {
            float4* dst = (float4*)(sw + ((ch + 1) & 1) * (KC * HDIM));
            #pragma unroll
            for (int k = 0; k < 3; ++k)
                dst[tid + THREADS * k] = wpre[k];
        }
        __syncthreads();
    }

    // ---- Phase 3: +b1, exact GELU, GEMM2 partials, half-warp reduce, store ----
    float part[4][3];
    #pragma unroll
    for (int i = 0; i < 4; ++i)
        #pragma unroll
        for (int co = 0; co < 3; ++co)
            part[i][co] = 0.f;

    #pragma unroll
    for (int i = 0; i < 4; ++i) {
        #pragma unroll
        for (int j = 0; j < 3; ++j) {
            const int c0 = 6 * cg + 2 * j;
            float y0 = __uint_as_float((unsigned)(acc[i][j] & 0xffffffffull)) + __ldg(&b1[c0]);
            float y1 = __uint_as_float((unsigned)(acc[i][j] >> 32)) + __ldg(&b1[c0 + 1]);
            const float g0 = gelu_exact(y0);
            const float g1 = gelu_exact(y1);
            #pragma unroll
            for (int co = 0; co < 3; ++co)
                part[i][co] += g0 * __ldg(&w2[c0 * 3 + co]) + g1 * __ldg(&w2[(c0 + 1) * 3 + co]);
        }
    }

    // reduce over the 16 cg threads of this row group (contiguous half-warp)
    #pragma unroll
    for (int m = 8; m > 0; m >>= 1) {
        #pragma unroll
        for (int i = 0; i < 4; ++i)
            #pragma unroll
            for (int co = 0; co < 3; ++co)
                part[i][co] += __shfl_xor_sync(0xffffffffu, part[i][co], m);
    }

    if (cg == 0) {
        #pragma unroll
        for (int i = 0; i < 4; ++i) {
            const long long r = rowbase + 4 * rg + i;
            #pragma unroll
            for (int co = 0; co < 3; ++co)
                out[r * 3 + co] = part[i][co] + __ldg(&b2[co]);
        }
    }
}

extern "C" void kernel_launch(void* const* d_in, const int* in_sizes, int n_in,
                              void* d_out, int out_size) {
    const float* emb   = (const float*)d_in[0];
    const float* tree  = (const float*)d_in[1];
    const float* gamma = (const float*)d_in[2];
    const float* beta  = (const float*)d_in[3];
    const float* w1    = (const float*)d_in[4];
    const float* b1    = (const float*)d_in[5];
    const float* w2    = (const float*)d_in[6];
    const float* b2    = (const float*)d_in[7];
    float* out = (float*)d_out;

    const int B = in_sizes[0] / 768;
    const size_t shmem = (size_t)(TB * XSTRIDE + 2 * KC * HDIM) * sizeof(float); // 222208 B

    cudaFuncSetAttribute(fusion_head_kernel,
                         cudaFuncAttributeMaxDynamicSharedMemorySize, (int)shmem);

    fusion_head_kernel<<<B / TB, THREADS, shmem>>>(emb, tree, gamma, beta,
                                                   w1, b1, w2, b2, out);
}

// round 5
// speedup vs baseline: 1.8239x; 1.8239x over previous
#include <cuda_runtime.h>
#include <cuda_bf16.h>
#include <math.h>
#include <stdint.h>

#define THREADS 256
#define TB      256          // rows per CTA (8 warps x 32 rows)
#define NCH     48           // 768 / 16
#define HD      96

// ---- precomputed weight data (device globals; allocation-free scratch) ----
// fragment-order bf16: [ch][j][lane][reg][half] -> u16
__device__ unsigned short g_Bhi16[NCH * 12 * 32 * 2 * 2];
__device__ unsigned short g_Blo16[NCH * 12 * 32 * 2 * 2];
__device__ float g_C1[HD];        // sum_d beta*w1 + b1
__device__ float g_C2[HD];        // sum_d gamma*w1 (all 771 d)
__device__ float g_WT[3 * HD];    // gamma[768+j]*w1[768+j][n]

// ======================= setup kernels =======================

__global__ void fh_prep_b(const float* __restrict__ gamma,
                          const float* __restrict__ w1) {
    const int idx = blockIdx.x * 256 + threadIdx.x;
    if (idx >= 768 * HD) return;
    const int k = idx / HD, n = idx % HD;
    const float wt = __ldg(&gamma[k]) * __ldg(&w1[(size_t)k * HD + n]);
    const __nv_bfloat16 hb = __float2bfloat16(wt);
    const float hf = __bfloat162float(hb);
    const __nv_bfloat16 lb = __float2bfloat16(wt - hf);
    const int ch = k >> 4, kk = k & 15;
    const int j = n >> 3, gg = n & 7;
    const int t = (kk & 7) >> 1, half = kk & 1, reg = kk >> 3;
    const int l = gg * 4 + t;
    const int off = ((((ch * 12 + j) * 32 + l) * 2 + reg) * 2 + half);
    g_Bhi16[off] = *(const unsigned short*)&hb;
    g_Blo16[off] = *(const unsigned short*)&lb;
}

__global__ void fh_prep_c(const float* __restrict__ gamma,
                          const float* __restrict__ beta,
                          const float* __restrict__ w1,
                          const float* __restrict__ b1) {
    const int n = blockIdx.x;            // 96 blocks
    const int tid = threadIdx.x;         // 256 threads
    float c1 = 0.f, c2 = 0.f;
    for (int k = tid; k < 768; k += 256) {
        const float w = __ldg(&w1[(size_t)k * HD + n]);
        c2 = fmaf(__ldg(&gamma[k]), w, c2);
        c1 = fmaf(__ldg(&beta[k]),  w, c1);
    }
    #pragma unroll
    for (int m = 16; m > 0; m >>= 1) {
        c1 += __shfl_xor_sync(0xffffffffu, c1, m);
        c2 += __shfl_xor_sync(0xffffffffu, c2, m);
    }
    __shared__ float s1[8], s2[8];
    if ((tid & 31) == 0) { s1[tid >> 5] = c1; s2[tid >> 5] = c2; }
    __syncthreads();
    if (tid == 0) {
        c1 = 0.f; c2 = 0.f;
        #pragma unroll
        for (int i = 0; i < 8; ++i) { c1 += s1[i]; c2 += s2[i]; }
        c1 += __ldg(&b1[n]);
        #pragma unroll
        for (int j = 0; j < 3; ++j) {
            const float w  = __ldg(&w1[(size_t)(768 + j) * HD + n]);
            const float wt = __ldg(&gamma[768 + j]) * w;
            g_WT[j * HD + n] = wt;
            c2 += wt;
            c1 = fmaf(__ldg(&beta[768 + j]), w, c1);
        }
        g_C1[n] = c1;
        g_C2[n] = c2;
    }
}

// ======================= main kernel =======================

__device__ __forceinline__ uint32_t pack_bf16x2(float hi, float lo) {
    uint32_t r;
    asm("cvt.rn.bf16x2.f32 %0, %1, %2;" : "=r"(r) : "f"(hi), "f"(lo));
    return r;
}

__device__ __forceinline__ void splitf2(float x, float y, uint32_t& hi, uint32_t& lo) {
    hi = pack_bf16x2(y, x);
    const float rx = x - __uint_as_float(hi << 16);
    const float ry = y - __uint_as_float(hi & 0xffff0000u);
    lo = pack_bf16x2(ry, rx);
}

__device__ __forceinline__ void mma16816(float* c, const uint32_t* a, uint2 b) {
    asm volatile(
        "mma.sync.aligned.m16n8k16.row.col.f32.bf16.bf16.f32 "
        "{%0,%1,%2,%3}, {%4,%5,%6,%7}, {%8,%9}, {%0,%1,%2,%3};\n"
        : "+f"(c[0]), "+f"(c[1]), "+f"(c[2]), "+f"(c[3])
        : "r"(a[0]), "r"(a[1]), "r"(a[2]), "r"(a[3]), "r"(b.x), "r"(b.y));
}

__device__ __forceinline__ void cpa16(uint32_t d, const void* s) {
    asm volatile("cp.async.cg.shared.global [%0], [%1], 16;" :: "r"(d), "l"(s) : "memory");
}

__device__ __forceinline__ uint32_t smem_u32(const void* p) {
    return (uint32_t)__cvta_generic_to_shared(p);
}

__global__ __launch_bounds__(THREADS)
void fh_main(const float* __restrict__ emb,
             const float* __restrict__ tree,
             const float* __restrict__ w2,
             const float* __restrict__ b2,
             float* __restrict__ out)
{
    __shared__ __align__(16) unsigned char sB[2][6144];   // per buf: [hi 3072][lo 3072]
    __shared__ float sC1[HD], sC2[HD], sWT[3 * HD], sW2[HD * 3];
    __shared__ float sMU[TB], sRS[TB], sT[TB * 3];

    const int tid = threadIdx.x;
    const int w   = tid >> 5;
    const int l   = tid & 31;
    const int g   = l >> 2;
    const int t   = l & 3;
    const size_t rowbase = (size_t)blockIdx.x * TB;
    const int wrow = w * 32;

    // tables
    if (tid < HD) { sC1[tid] = g_C1[tid]; sC2[tid] = g_C2[tid]; }
    for (int i = tid; i < 3 * HD; i += THREADS) {
        sWT[i] = g_WT[i];
        sW2[i] = __ldg(&w2[i]);
    }

    // prefetch chunk 0
    if (tid < 192) {
        cpa16(smem_u32(&sB[0][tid * 16]),        (const char*)g_Bhi16 + tid * 16);
        cpa16(smem_u32(&sB[0][3072 + tid * 16]), (const char*)g_Blo16 + tid * 16);
    }
    asm volatile("cp.async.commit_group;" ::: "memory");

    float acc[2][12][4];
    #pragma unroll
    for (int rt = 0; rt < 2; ++rt)
        #pragma unroll
        for (int j = 0; j < 12; ++j)
            #pragma unroll
            for (int c = 0; c < 4; ++c) acc[rt][j][c] = 0.f;

    float s4[4] = {0.f, 0.f, 0.f, 0.f};
    float q4[4] = {0.f, 0.f, 0.f, 0.f};

    // row pointers for (rt,h): row = wrow + 16*rt + 8*h + g, col offset 2t
    const float* rp[4];
    #pragma unroll
    for (int rt = 0; rt < 2; ++rt)
        #pragma unroll
        for (int h = 0; h < 2; ++h)
            rp[rt * 2 + h] = emb + (rowbase + wrow + 16 * rt + 8 * h + g) * 768 + 2 * t;

    #pragma unroll 1
    for (int ch = 0; ch < NCH; ++ch) {
        // ---- A: load, stats, split to bf16 hi/lo fragments ----
        uint32_t ahi[2][4], alo[2][4];
        #pragma unroll
        for (int rt = 0; rt < 2; ++rt) {
            #pragma unroll
            for (int h = 0; h < 2; ++h) {
                const int idx = rt * 2 + h;
                const float* p = rp[idx] + ch * 16;
                const float2 v0 = __ldg((const float2*)p);
                const float2 v1 = __ldg((const float2*)(p + 8));
                splitf2(v0.x, v0.y, ahi[rt][h],     alo[rt][h]);
                splitf2(v1.x, v1.y, ahi[rt][h + 2], alo[rt][h + 2]);
                s4[idx] += (v0.x + v0.y) + (v1.x + v1.y);
                q4[idx] = fmaf(v0.x, v0.x, q4[idx]);
                q4[idx] = fmaf(v0.y, v0.y, q4[idx]);
                q4[idx] = fmaf(v1.x, v1.x, q4[idx]);
                q4[idx] = fmaf(v1.y, v1.y, q4[idx]);
            }
        }

        // ---- prefetch next B chunk, wait for current ----
        if (ch + 1 < NCH) {
            if (tid < 192) {
                const int buf = (ch + 1) & 1;
                cpa16(smem_u32(&sB[buf][tid * 16]),
                      (const char*)g_Bhi16 + (ch + 1) * 3072 + tid * 16);
                cpa16(smem_u32(&sB[buf][3072 + tid * 16]),
                      (const char*)g_Blo16 + (ch + 1) * 3072 + tid * 16);
            }
            asm volatile("cp.async.commit_group;" ::: "memory");
            asm volatile("cp.async.wait_group 1;" ::: "memory");
        } else {
            asm volatile("cp.async.wait_group 0;" ::: "memory");
        }
        __syncthreads();

        // ---- MMAs: 3 passes so same-acc dependencies are 24 MMAs apart ----
        const unsigned char* base = sB[ch & 1];
        uint2 bh[12];
        #pragma unroll
        for (int j = 0; j < 12; ++j)
            bh[j] = *(const uint2*)(base + j * 256 + l * 8);
        #pragma unroll
        for (int j = 0; j < 12; ++j) {
            mma16816(acc[0][j], ahi[0], bh[j]);
            mma16816(acc[1][j], ahi[1], bh[j]);
        }
        #pragma unroll
        for (int j = 0; j < 12; ++j) {
            mma16816(acc[0][j], alo[0], bh[j]);
            mma16816(acc[1][j], alo[1], bh[j]);
        }
        #pragma unroll
        for (int j = 0; j < 12; ++j) {
            const uint2 bl = *(const uint2*)(base + 3072 + j * 256 + l * 8);
            mma16816(acc[0][j], ahi[0], bl);
            mma16816(acc[1][j], ahi[1], bl);
        }
        __syncthreads();   // everyone done reading before this buf is refilled
    }

    // ---- row stats: reduce over the 4 quad lanes, add tree tail ----
    #pragma unroll
    for (int m = 1; m <= 2; m <<= 1) {
        #pragma unroll
        for (int idx = 0; idx < 4; ++idx) {
            s4[idx] += __shfl_xor_sync(0xffffffffu, s4[idx], m);
            q4[idx] += __shfl_xor_sync(0xffffffffu, q4[idx], m);
        }
    }
    if (t == 0) {
        #pragma unroll
        for (int idx = 0; idx < 4; ++idx) {
            const int lr = wrow + 16 * (idx >> 1) + 8 * (idx & 1) + g;
            const size_t gr = rowbase + lr;
            const float t0 = __ldg(&tree[gr * 3 + 0]);
            const float t1 = __ldg(&tree[gr * 3 + 1]);
            const float t2 = __ldg(&tree[gr * 3 + 2]);
            const float s = s4[idx] + t0 + t1 + t2;
            const float q = q4[idx] + t0 * t0 + t1 * t1 + t2 * t2;
            const float mu = s * (1.0f / 771.0f);
            const float rs = rsqrtf(q * (1.0f / 771.0f) - mu * mu + 1e-5f);
            sMU[lr] = mu; sRS[lr] = rs;
            sT[lr * 3 + 0] = t0; sT[lr * 3 + 1] = t1; sT[lr * 3 + 2] = t2;
        }
    }
    __syncthreads();

    // ---- epilogue: LN-fold + bias + exact GELU + GEMM2 partials ----
    float mu[4], rs[4], tv[4][3];
    #pragma unroll
    for (int idx = 0; idx < 4; ++idx) {
        const int lr = wrow + 16 * (idx >> 1) + 8 * (idx & 1) + g;
        mu[idx] = sMU[lr]; rs[idx] = sRS[lr];
        tv[idx][0] = sT[lr * 3 + 0];
        tv[idx][1] = sT[lr * 3 + 1];
        tv[idx][2] = sT[lr * 3 + 2];
    }
    float o[4][3];
    #pragma unroll
    for (int idx = 0; idx < 4; ++idx)
        #pragma unroll
        for (int c = 0; c < 3; ++c) o[idx][c] = 0.f;

    #pragma unroll
    for (int j = 0; j < 12; ++j) {
        const int n0 = 8 * j + 2 * t;
        float c2v[2] = {sC2[n0], sC2[n0 + 1]};
        float c1v[2] = {sC1[n0], sC1[n0 + 1]};
        float wt0[2] = {sWT[n0], sWT[n0 + 1]};
        float wt1[2] = {sWT[HD + n0], sWT[HD + n0 + 1]};
        float wt2[2] = {sWT[2 * HD + n0], sWT[2 * HD + n0 + 1]};
        float w2v[2][3];
        #pragma unroll
        for (int cc = 0; cc < 2; ++cc)
            #pragma unroll
            for (int c = 0; c < 3; ++c)
                w2v[cc][c] = sW2[(n0 + cc) * 3 + c];

        #pragma unroll
        for (int rt = 0; rt < 2; ++rt) {
            #pragma unroll
            for (int h = 0; h < 2; ++h) {
                const int idx = rt * 2 + h;
                #pragma unroll
                for (int cc = 0; cc < 2; ++cc) {
                    const float a = acc[rt][j][2 * h + cc];
                    const float tail = tv[idx][0] * wt0[cc] +
                                       tv[idx][1] * wt1[cc] +
                                       tv[idx][2] * wt2[cc];
                    const float y = rs[idx] * (a + tail - mu[idx] * c2v[cc]) + c1v[cc];
                    const float gl = 0.5f * y * (1.0f + erff(y * 0.70710678118654752f));
                    o[idx][0] = fmaf(gl, w2v[cc][0], o[idx][0]);
                    o[idx][1] = fmaf(gl, w2v[cc][1], o[idx][1]);
                    o[idx][2] = fmaf(gl, w2v[cc][2], o[idx][2]);
                }
            }
        }
    }

    #pragma unroll
    for (int m = 1; m <= 2; m <<= 1)
        #pragma unroll
        for (int idx = 0; idx < 4; ++idx)
            #pragma unroll
            for (int c = 0; c < 3; ++c)
                o[idx][c] += __shfl_xor_sync(0xffffffffu, o[idx][c], m);

    if (t == 0) {
        const float b20 = __ldg(&b2[0]);
        const float b21 = __ldg(&b2[1]);
        const float b22 = __ldg(&b2[2]);
        #pragma unroll
        for (int idx = 0; idx < 4; ++idx) {
            const int lr = wrow + 16 * (idx >> 1) + 8 * (idx & 1) + g;
            const size_t gr = rowbase + lr;
            out[gr * 3 + 0] = o[idx][0] + b20;
            out[gr * 3 + 1] = o[idx][1] + b21;
            out[gr * 3 + 2] = o[idx][2] + b22;
        }
    }
}

extern "C" void kernel_launch(void* const* d_in, const int* in_sizes, int n_in,
                              void* d_out, int out_size) {
    const float* emb   = (const float*)d_in[0];
    const float* tree  = (const float*)d_in[1];
    const float* gamma = (const float*)d_in[2];
    const float* beta  = (const float*)d_in[3];
    const float* w1    = (const float*)d_in[4];
    const float* b1    = (const float*)d_in[5];
    const float* w2    = (const float*)d_in[6];
    const float* b2    = (const float*)d_in[7];
    float* out = (float*)d_out;

    const int B = in_sizes[0] / 768;

    fh_prep_b<<<(768 * HD + 255) / 256, 256>>>(gamma, w1);
    fh_prep_c<<<HD, 256>>>(gamma, beta, w1, b1);
    fh_main<<<B / TB, THREADS>>>(emb, tree, w2, b2, out);
}

// round 6
// speedup vs baseline: 1.8292x; 1.0029x over previous
#include <cuda_runtime.h>
#include <cuda_bf16.h>
#include <math.h>
#include <stdint.h>

#define THREADS 256
#define TB      256          // rows per CTA (8 warps x 32 rows)
#define NCH     48           // 768 / 16
#define HD      96

// ---- precomputed weight data (device globals; allocation-free scratch) ----
// fragment-order bf16: [ch][j][lane][reg][half] -> u16
__device__ unsigned short g_Bhi16[NCH * 12 * 32 * 2 * 2];
__device__ unsigned short g_Blo16[NCH * 12 * 32 * 2 * 2];
__device__ float g_C1[HD];        // sum_d beta*w1 + b1
__device__ float g_C2[HD];        // sum_d gamma*w1 (all 771 d)
__device__ float g_WT[3 * HD];    // gamma[768+j]*w1[768+j][n]

// ======================= setup kernels =======================

__global__ void fh_prep_b(const float* __restrict__ gamma,
                          const float* __restrict__ w1) {
    const int idx = blockIdx.x * 256 + threadIdx.x;
    if (idx >= 768 * HD) return;
    const int k = idx / HD, n = idx % HD;
    const float wt = __ldg(&gamma[k]) * __ldg(&w1[(size_t)k * HD + n]);
    const __nv_bfloat16 hb = __float2bfloat16(wt);
    const float hf = __bfloat162float(hb);
    const __nv_bfloat16 lb = __float2bfloat16(wt - hf);
    const int ch = k >> 4, kk = k & 15;
    const int j = n >> 3, gg = n & 7;
    const int t = (kk & 7) >> 1, half = kk & 1, reg = kk >> 3;
    const int l = gg * 4 + t;
    const int off = ((((ch * 12 + j) * 32 + l) * 2 + reg) * 2 + half);
    g_Bhi16[off] = *(const unsigned short*)&hb;
    g_Blo16[off] = *(const unsigned short*)&lb;
}

__global__ void fh_prep_c(const float* __restrict__ gamma,
                          const float* __restrict__ beta,
                          const float* __restrict__ w1,
                          const float* __restrict__ b1) {
    const int n = blockIdx.x;            // 96 blocks
    const int tid = threadIdx.x;         // 256 threads
    float c1 = 0.f, c2 = 0.f;
    for (int k = tid; k < 768; k += 256) {
        const float w = __ldg(&w1[(size_t)k * HD + n]);
        c2 = fmaf(__ldg(&gamma[k]), w, c2);
        c1 = fmaf(__ldg(&beta[k]),  w, c1);
    }
    #pragma unroll
    for (int m = 16; m > 0; m >>= 1) {
        c1 += __shfl_xor_sync(0xffffffffu, c1, m);
        c2 += __shfl_xor_sync(0xffffffffu, c2, m);
    }
    __shared__ float s1[8], s2[8];
    if ((tid & 31) == 0) { s1[tid >> 5] = c1; s2[tid >> 5] = c2; }
    __syncthreads();
    if (tid == 0) {
        c1 = 0.f; c2 = 0.f;
        #pragma unroll
        for (int i = 0; i < 8; ++i) { c1 += s1[i]; c2 += s2[i]; }
        c1 += __ldg(&b1[n]);
        #pragma unroll
        for (int j = 0; j < 3; ++j) {
            const float w  = __ldg(&w1[(size_t)(768 + j) * HD + n]);
            const float wt = __ldg(&gamma[768 + j]) * w;
            g_WT[j * HD + n] = wt;
            c2 += wt;
            c1 = fmaf(__ldg(&beta[768 + j]), w, c1);
        }
        g_C1[n] = c1;
        g_C2[n] = c2;
    }
}

// ======================= main kernel =======================

__device__ __forceinline__ uint32_t pack_bf16x2(float hi, float lo) {
    uint32_t r;
    asm("cvt.rn.bf16x2.f32 %0, %1, %2;" : "=r"(r) : "f"(hi), "f"(lo));
    return r;
}

__device__ __forceinline__ void splitf2(float x, float y, uint32_t& hi, uint32_t& lo) {
    hi = pack_bf16x2(y, x);
    const float rx = x - __uint_as_float(hi << 16);
    const float ry = y - __uint_as_float(hi & 0xffff0000u);
    lo = pack_bf16x2(ry, rx);
}

__device__ __forceinline__ void mma16816(float* c, const uint32_t* a, uint2 b) {
    asm volatile(
        "mma.sync.aligned.m16n8k16.row.col.f32.bf16.bf16.f32 "
        "{%0,%1,%2,%3}, {%4,%5,%6,%7}, {%8,%9}, {%0,%1,%2,%3};\n"
        : "+f"(c[0]), "+f"(c[1]), "+f"(c[2]), "+f"(c[3])
        : "r"(a[0]), "r"(a[1]), "r"(a[2]), "r"(a[3]), "r"(b.x), "r"(b.y));
}

__device__ __forceinline__ void cpa16(uint32_t d, const void* s) {
    asm volatile("cp.async.cg.shared.global [%0], [%1], 16;" :: "r"(d), "l"(s) : "memory");
}

__device__ __forceinline__ uint32_t smem_u32(const void* p) {
    return (uint32_t)__cvta_generic_to_shared(p);
}

__global__ __launch_bounds__(THREADS)
void fh_main(const float* __restrict__ emb,
             const float* __restrict__ tree,
             const float* __restrict__ w2,
             const float* __restrict__ b2,
             float* __restrict__ out)
{
    __shared__ __align__(16) unsigned char sB[2][6144];   // per buf: [hi 3072][lo 3072]
    __shared__ float sC1[HD], sC2[HD], sWT[3 * HD], sW2[HD * 3];
    __shared__ float sMU[TB], sRS[TB], sT[TB * 3];

    const int tid = threadIdx.x;
    const int w   = tid >> 5;
    const int l   = tid & 31;
    const int g   = l >> 2;
    const int t   = l & 3;
    const size_t rowbase = (size_t)blockIdx.x * TB;
    const int wrow = w * 32;

    // tables
    if (tid < HD) { sC1[tid] = g_C1[tid]; sC2[tid] = g_C2[tid]; }
    for (int i = tid; i < 3 * HD; i += THREADS) {
        sWT[i] = g_WT[i];
        sW2[i] = __ldg(&w2[i]);
    }

    // prefetch chunk 0
    if (tid < 192) {
        cpa16(smem_u32(&sB[0][tid * 16]),        (const char*)g_Bhi16 + tid * 16);
        cpa16(smem_u32(&sB[0][3072 + tid * 16]), (const char*)g_Blo16 + tid * 16);
    }
    asm volatile("cp.async.commit_group;" ::: "memory");

    float acc[2][12][4];
    #pragma unroll
    for (int rt = 0; rt < 2; ++rt)
        #pragma unroll
        for (int j = 0; j < 12; ++j)
            #pragma unroll
            for (int c = 0; c < 4; ++c) acc[rt][j][c] = 0.f;

    float s4[4] = {0.f, 0.f, 0.f, 0.f};
    float q4[4] = {0.f, 0.f, 0.f, 0.f};

    // row pointers for (rt,h): row = wrow + 16*rt + 8*h + g, col offset 2t
    const float* rp[4];
    #pragma unroll
    for (int rt = 0; rt < 2; ++rt)
        #pragma unroll
        for (int h = 0; h < 2; ++h)
            rp[rt * 2 + h] = emb + (rowbase + wrow + 16 * rt + 8 * h + g) * 768 + 2 * t;

    #pragma unroll 1
    for (int ch = 0; ch < NCH; ++ch) {
        // ---- A: load, stats, split to bf16 hi/lo fragments ----
        uint32_t ahi[2][4], alo[2][4];
        #pragma unroll
        for (int rt = 0; rt < 2; ++rt) {
            #pragma unroll
            for (int h = 0; h < 2; ++h) {
                const int idx = rt * 2 + h;
                const float* p = rp[idx] + ch * 16;
                const float2 v0 = __ldg((const float2*)p);
                const float2 v1 = __ldg((const float2*)(p + 8));
                splitf2(v0.x, v0.y, ahi[rt][h],     alo[rt][h]);
                splitf2(v1.x, v1.y, ahi[rt][h + 2], alo[rt][h + 2]);
                s4[idx] += (v0.x + v0.y) + (v1.x + v1.y);
                q4[idx] = fmaf(v0.x, v0.x, q4[idx]);
                q4[idx] = fmaf(v0.y, v0.y, q4[idx]);
                q4[idx] = fmaf(v1.x, v1.x, q4[idx]);
                q4[idx] = fmaf(v1.y, v1.y, q4[idx]);
            }
        }

        // ---- prefetch next B chunk, wait for current ----
        if (ch + 1 < NCH) {
            if (tid < 192) {
                const int buf = (ch + 1) & 1;
                cpa16(smem_u32(&sB[buf][tid * 16]),
                      (const char*)g_Bhi16 + (ch + 1) * 3072 + tid * 16);
                cpa16(smem_u32(&sB[buf][3072 + tid * 16]),
                      (const char*)g_Blo16 + (ch + 1) * 3072 + tid * 16);
            }
            asm volatile("cp.async.commit_group;" ::: "memory");
            asm volatile("cp.async.wait_group 1;" ::: "memory");
        } else {
            asm volatile("cp.async.wait_group 0;" ::: "memory");
        }
        __syncthreads();

        // ---- MMAs: 3 passes so same-acc dependencies are 24 MMAs apart ----
        const unsigned char* base = sB[ch & 1];
        uint2 bh[12];
        #pragma unroll
        for (int j = 0; j < 12; ++j)
            bh[j] = *(const uint2*)(base + j * 256 + l * 8);
        #pragma unroll
        for (int j = 0; j < 12; ++j) {
            mma16816(acc[0][j], ahi[0], bh[j]);
            mma16816(acc[1][j], ahi[1], bh[j]);
        }
        #pragma unroll
        for (int j = 0; j < 12; ++j) {
            mma16816(acc[0][j], alo[0], bh[j]);
            mma16816(acc[1][j], alo[1], bh[j]);
        }
        #pragma unroll
        for (int j = 0; j < 12; ++j) {
            const uint2 bl = *(const uint2*)(base + 3072 + j * 256 + l * 8);
            mma16816(acc[0][j], ahi[0], bl);
            mma16816(acc[1][j], ahi[1], bl);
        }
        __syncthreads();   // everyone done reading before this buf is refilled
    }

    // ---- row stats: reduce over the 4 quad lanes, add tree tail ----
    #pragma unroll
    for (int m = 1; m <= 2; m <<= 1) {
        #pragma unroll
        for (int idx = 0; idx < 4; ++idx) {
            s4[idx] += __shfl_xor_sync(0xffffffffu, s4[idx], m);
            q4[idx] += __shfl_xor_sync(0xffffffffu, q4[idx], m);
        }
    }
    if (t == 0) {
        #pragma unroll
        for (int idx = 0; idx < 4; ++idx) {
            const int lr = wrow + 16 * (idx >> 1) + 8 * (idx & 1) + g;
            const size_t gr = rowbase + lr;
            const float t0 = __ldg(&tree[gr * 3 + 0]);
            const float t1 = __ldg(&tree[gr * 3 + 1]);
            const float t2 = __ldg(&tree[gr * 3 + 2]);
            const float s = s4[idx] + t0 + t1 + t2;
            const float q = q4[idx] + t0 * t0 + t1 * t1 + t2 * t2;
            const float mu = s * (1.0f / 771.0f);
            const float rs = rsqrtf(q * (1.0f / 771.0f) - mu * mu + 1e-5f);
            sMU[lr] = mu; sRS[lr] = rs;
            sT[lr * 3 + 0] = t0; sT[lr * 3 + 1] = t1; sT[lr * 3 + 2] = t2;
        }
    }
    __syncthreads();

    // ---- epilogue: LN-fold + bias + exact GELU + GEMM2 partials ----
    float mu[4], rs[4], tv[4][3];
    #pragma unroll
    for (int idx = 0; idx < 4; ++idx) {
        const int lr = wrow + 16 * (idx >> 1) + 8 * (idx & 1) + g;
        mu[idx] = sMU[lr]; rs[idx] = sRS[lr];
        tv[idx][0] = sT[lr * 3 + 0];
        tv[idx][1] = sT[lr * 3 + 1];
        tv[idx][2] = sT[lr * 3 + 2];
    }
    float o[4][3];
    #pragma unroll
    for (int idx = 0; idx < 4; ++idx)
        #pragma unroll
        for (int c = 0; c < 3; ++c) o[idx][c] = 0.f;

    #pragma unroll
    for (int j = 0; j < 12; ++j) {
        const int n0 = 8 * j + 2 * t;
        float c2v[2] = {sC2[n0], sC2[n0 + 1]};
        float c1v[2] = {sC1[n0], sC1[n0 + 1]};
        float wt0[2] = {sWT[n0], sWT[n0 + 1]};
        float wt1[2] = {sWT[HD + n0], sWT[HD + n0 + 1]};
        float wt2[2] = {sWT[2 * HD + n0], sWT[2 * HD + n0 + 1]};
        float w2v[2][3];
        #pragma unroll
        for (int cc = 0; cc < 2; ++cc)
            #pragma unroll
            for (int c = 0; c < 3; ++c)
                w2v[cc][c] = sW2[(n0 + cc) * 3 + c];

        #pragma unroll
        for (int rt = 0; rt < 2; ++rt) {
            #pragma unroll
            for (int h = 0; h < 2; ++h) {
                const int idx = rt * 2 + h;
                #pragma unroll
                for (int cc = 0; cc < 2; ++cc) {
                    const float a = acc[rt][j][2 * h + cc];
                    const float tail = tv[idx][0] * wt0[cc] +
                                       tv[idx][1] * wt1[cc] +
                                       tv[idx][2] * wt2[cc];
                    const float y = rs[idx] * (a + tail - mu[idx] * c2v[cc]) + c1v[cc];
                    const float gl = 0.5f * y * (1.0f + erff(y * 0.70710678118654752f));
                    o[idx][0] = fmaf(gl, w2v[cc][0], o[idx][0]);
                    o[idx][1] = fmaf(gl, w2v[cc][1], o[idx][1]);
                    o[idx][2] = fmaf(gl, w2v[cc][2], o[idx][2]);
                }
            }
        }
    }

    #pragma unroll
    for (int m = 1; m <= 2; m <<= 1)
        #pragma unroll
        for (int idx = 0; idx < 4; ++idx)
            #pragma unroll
            for (int c = 0; c < 3; ++c)
                o[idx][c] += __shfl_xor_sync(0xffffffffu, o[idx][c], m);

    if (t == 0) {
        const float b20 = __ldg(&b2[0]);
        const float b21 = __ldg(&b2[1]);
        const float b22 = __ldg(&b2[2]);
        #pragma unroll
        for (int idx = 0; idx < 4; ++idx) {
            const int lr = wrow + 16 * (idx >> 1) + 8 * (idx & 1) + g;
            const size_t gr = rowbase + lr;
            out[gr * 3 + 0] = o[idx][0] + b20;
            out[gr * 3 + 1] = o[idx][1] + b21;
            out[gr * 3 + 2] = o[idx][2] + b22;
        }
    }
}

extern "C" void kernel_launch(void* const* d_in, const int* in_sizes, int n_in,
                              void* d_out, int out_size) {
    const float* emb   = (const float*)d_in[0];
    const float* tree  = (const float*)d_in[1];
    const float* gamma = (const float*)d_in[2];
    const float* beta  = (const float*)d_in[3];
    const float* w1    = (const float*)d_in[4];
    const float* b1    = (const float*)d_in[5];
    const float* w2    = (const float*)d_in[6];
    const float* b2    = (const float*)d_in[7];
    float* out = (float*)d_out;

    const int B = in_sizes[0] / 768;

    fh_prep_b<<<(768 * HD + 255) / 256, 256>>>(gamma, w1);
    fh_prep_c<<<HD, 256>>>(gamma, beta, w1, b1);
    fh_main<<<B / TB, THREADS>>>(emb, tree, w2, b2, out);
}